// round 13
// baseline (speedup 1.0000x reference)
#include <cuda_runtime.h>
#include <cuda_bf16.h>
#include <cstdint>

#define H 128
#define MAXN 100000
#define MAXE 600000
#define MAXNP (MAXN + 128)   // pad so unguarded tail-tile accesses stay in bounds

// ---------------------------------------------------------------------------
// Scratch (__device__ globals; no allocation allowed)
// ---------------------------------------------------------------------------
__device__ float g_x[MAXNP * H];                       // fp32 node features
// Packed activations: per row, 32 uint4 groups; group (kc,tig) at index kc*4+tig
// = {hi(k,k+1), hi(k+8,k+9), lo(k,k+1), lo(k+8,k+9)}, k = kc*16 + tig*2.
__device__ unsigned short g_aggp[MAXNP * H * 2];       // packed agg (MLP input)
// Packed B fragments (weights), built once per call.
__device__ unsigned short g_Bpack[6 * 128 * 32 * 8];
// CSR
__device__ int g_rowptr[MAXN + 1];
__device__ int g_off[MAXN];
__device__ int g_bsum[128];
__device__ int g_eid[MAXE];

// ---------------------------------------------------------------------------
// Prep: packed B fragments + zero g_off (CSR hist init) + batch tail output.
// ---------------------------------------------------------------------------
__global__ void prep_kernel(const float* __restrict__ W1,
                            const float* __restrict__ W2,
                            const int* __restrict__ bat,
                            float* __restrict__ otail,
                            int N)
{
    int i = blockIdx.x * blockDim.x + threadIdx.x;

    if (i < 6 * 128 * 32) {
        int g = i;
        int mat = g >> 12;
        int r = g & 4095;
        int nrow = r >> 5;
        int q = r & 31;
        int kc = q >> 2;
        int tig = q & 3;
        int k = kc * 16 + tig * 2;

        const float* W = (mat < 3) ? (W1 + (size_t)mat * H * H)
                                   : (W2 + (size_t)(mat - 3) * H * H);
        unsigned short s[8];
        int kk[4] = {k, k + 1, k + 8, k + 9};
        #pragma unroll
        for (int j = 0; j < 4; j++) {
            float v = W[kk[j] * H + nrow];
            __nv_bfloat16 hi = __float2bfloat16(v);
            float res = v - __bfloat162float(hi);
            __nv_bfloat16 lo = __float2bfloat16(res);
            s[j] = __bfloat16_as_ushort(hi);
            s[4 + j] = __bfloat16_as_ushort(lo);
        }
        uint4 out;
        out.x = (uint32_t)s[0] | ((uint32_t)s[1] << 16);
        out.y = (uint32_t)s[2] | ((uint32_t)s[3] << 16);
        out.z = (uint32_t)s[4] | ((uint32_t)s[5] << 16);
        out.w = (uint32_t)s[6] | ((uint32_t)s[7] << 16);
        ((uint4*)g_Bpack)[g] = out;
    }
    if (i < N) {
        g_off[i] = 0;
        if (otail) otail[i] = (float)bat[i];
    }
}

// ---------------------------------------------------------------------------
// CSR build (once per call; graph static across layers)
// ---------------------------------------------------------------------------
__global__ void csr_hist_kernel(const int* __restrict__ dst, int E)
{
    int e = blockIdx.x * blockDim.x + threadIdx.x;
    if (e < E) atomicAdd(&g_off[dst[e]], 1);
}
__global__ void csr_scan1_kernel(int N)
{
    __shared__ int ts[256];
    int b = blockIdx.x, t = threadIdx.x;
    int base = b * 1024 + t * 4;
    int v0 = (base + 0 < N) ? g_off[base + 0] : 0;
    int v1 = (base + 1 < N) ? g_off[base + 1] : 0;
    int v2 = (base + 2 < N) ? g_off[base + 2] : 0;
    int v3 = (base + 3 < N) ? g_off[base + 3] : 0;
    int s = v0 + v1 + v2 + v3;
    ts[t] = s;
    __syncthreads();
    for (int d = 1; d < 256; d <<= 1) {
        int xv = (t >= d) ? ts[t - d] : 0;
        __syncthreads();
        ts[t] += xv;
        __syncthreads();
    }
    int run = ts[t] - s;
    if (t == 255) g_bsum[b] = ts[255];
    if (base + 0 < N) g_rowptr[base + 0] = run;  run += v0;
    if (base + 1 < N) g_rowptr[base + 1] = run;  run += v1;
    if (base + 2 < N) g_rowptr[base + 2] = run;  run += v2;
    if (base + 3 < N) g_rowptr[base + 3] = run;
}
__global__ void csr_scan2_kernel(int nb, int N, int E)
{
    __shared__ int sv[128];
    int t = threadIdx.x;
    if (t < nb) sv[t] = g_bsum[t];
    __syncthreads();
    if (t == 0) {
        int run = 0;
        for (int i = 0; i < nb; i++) { int v = sv[i]; sv[i] = run; run += v; }
        g_rowptr[N] = E;
    }
    __syncthreads();
    if (t < nb) g_bsum[t] = sv[t];
}
__global__ void csr_scan3_kernel(int N)
{
    int i = blockIdx.x * blockDim.x + threadIdx.x;
    if (i < N) {
        int r = g_rowptr[i] + g_bsum[i >> 10];
        g_rowptr[i] = r;
        g_off[i] = r;
    }
}
__global__ void csr_scatter_kernel(const int* __restrict__ dst, int E)
{
    int e = blockIdx.x * blockDim.x + threadIdx.x;
    if (e < E) {
        int pos = atomicAdd(&g_off[dst[e]], 1);
        g_eid[pos] = e;
    }
}

// ---------------------------------------------------------------------------
// Aggregate (CSR, no atomics): one warp per node; output packed bf16 hi/lo.
// Layer 0 reads node features from the L1-resident emb table via z[] (use_emb),
// later layers from x. Depth-1 software pipeline on the eid->src->ea chain.
// ---------------------------------------------------------------------------
__global__ __launch_bounds__(256) void agg_pack_kernel(
    const float* __restrict__ x,
    const float* __restrict__ emb,
    const int* __restrict__ z,
    const int* __restrict__ src,
    const float* __restrict__ ea,
    const float* __restrict__ We,
    const float* __restrict__ be,
    unsigned short* __restrict__ Apack,
    int N, int use_emb)
{
    int warp = (blockIdx.x * blockDim.x + threadIdx.x) >> 5;
    if (warp >= N) return;
    const int n = warp;
    const int lane = threadIdx.x & 31;
    const int k0 = ((lane >> 2) << 4) + ((lane & 3) << 1);

    const float2 w0a = *(const float2*)(We + 0 * H + k0);
    const float2 w0b = *(const float2*)(We + 0 * H + k0 + 8);
    const float2 w1a = *(const float2*)(We + 1 * H + k0);
    const float2 w1b = *(const float2*)(We + 1 * H + k0 + 8);
    const float2 w2a = *(const float2*)(We + 2 * H + k0);
    const float2 w2b = *(const float2*)(We + 2 * H + k0 + 8);
    const float2 w3a = *(const float2*)(We + 3 * H + k0);
    const float2 w3b = *(const float2*)(We + 3 * H + k0 + 8);
    const float2 bea = *(const float2*)(be + k0);
    const float2 beb = *(const float2*)(be + k0 + 8);

    // self row
    const float* selfrow = use_emb ? (emb + (size_t)__ldg(z + n) * H)
                                   : (x + (size_t)n * H);
    float2 sa = *(const float2*)(selfrow + k0);
    float2 sb = *(const float2*)(selfrow + k0 + 8);

    const int beg = g_rowptr[n], end = g_rowptr[n + 1];

    if (beg < end) {
        // pipeline depth 1: (e, srow, av)
        int e = __ldg(g_eid + beg);
        int s = __ldg(src + e);
        const float* srow = use_emb ? (emb + (size_t)__ldg(z + s) * H)
                                    : (x + (size_t)s * H);
        float4 av = *(const float4*)(ea + 4 * (size_t)e);

        for (int i = beg; i < end; i++) {
            const float* cur = srow;
            float4 a = av;
            if (i + 1 < end) {
                int e2 = __ldg(g_eid + i + 1);
                int s2 = __ldg(src + e2);
                srow = use_emb ? (emb + (size_t)__ldg(z + s2) * H)
                               : (x + (size_t)s2 * H);
                av = *(const float4*)(ea + 4 * (size_t)e2);
            }

            float2 pa, pb;
            pa.x = bea.x + a.x * w0a.x + a.y * w1a.x + a.z * w2a.x + a.w * w3a.x;
            pa.y = bea.y + a.x * w0a.y + a.y * w1a.y + a.z * w2a.y + a.w * w3a.y;
            pb.x = beb.x + a.x * w0b.x + a.y * w1b.x + a.z * w2b.x + a.w * w3b.x;
            pb.y = beb.y + a.x * w0b.y + a.y * w1b.y + a.z * w2b.y + a.w * w3b.y;

            float2 xa = *(const float2*)(cur + k0);
            float2 xb = *(const float2*)(cur + k0 + 8);
            sa.x += fmaxf(xa.x + pa.x, 0.0f);
            sa.y += fmaxf(xa.y + pa.y, 0.0f);
            sb.x += fmaxf(xb.x + pb.x, 0.0f);
            sb.y += fmaxf(xb.y + pb.y, 0.0f);
        }
    }

    __nv_bfloat162 ha = __floats2bfloat162_rn(sa.x, sa.y);
    __nv_bfloat162 hb = __floats2bfloat162_rn(sb.x, sb.y);
    __nv_bfloat162 la = __floats2bfloat162_rn(sa.x - __low2float(ha), sa.y - __high2float(ha));
    __nv_bfloat162 lb = __floats2bfloat162_rn(sb.x - __low2float(hb), sb.y - __high2float(hb));
    uint4 pk;
    pk.x = *(uint32_t*)&ha; pk.y = *(uint32_t*)&hb;
    pk.z = *(uint32_t*)&la; pk.w = *(uint32_t*)&lb;
    ((uint4*)Apack)[(size_t)n * 32 + lane] = pk;
}

// ---------------------------------------------------------------------------
// Fused MLP (both GEMMs, one kernel), split-bf16 fp32 emulation:
//   X' = (silu(A @ W1 + b1)) @ W2 + b2
// Warp w's gemm1 C-fragments for tiles nt=2kc,2kc+1 ARE the gemm2 A-fragment
// for k-chunk kc. U never touches gmem: hi via 32KB smem, lo in registers.
// ---------------------------------------------------------------------------
#define BROW 576
#define U_OFF (128 * BROW)                         // 73728
#define MLP_SMEM (U_OFF + 32768)                   // 106496 B -> 2 CTAs/SM

__device__ __forceinline__ void mma_bf16(float* c, const uint32_t* a,
                                         uint32_t b0, uint32_t b1)
{
    asm volatile(
        "mma.sync.aligned.m16n8k16.row.col.f32.bf16.bf16.f32 "
        "{%0,%1,%2,%3}, {%4,%5,%6,%7}, {%8,%9}, {%0,%1,%2,%3};"
        : "+f"(c[0]), "+f"(c[1]), "+f"(c[2]), "+f"(c[3])
        : "r"(a[0]), "r"(a[1]), "r"(a[2]), "r"(a[3]), "r"(b0), "r"(b1));
}

__device__ __forceinline__ float silu(float v) { return v / (1.0f + __expf(-v)); }

__device__ __forceinline__ void stage_B(char* smraw, int mat, int tid)
{
    const uint4* gp = (const uint4*)g_Bpack + (size_t)mat * 4096;
    #pragma unroll
    for (int it = 0; it < 16; it++) {
        int i = tid + it * 256;
        int row = i >> 5;
        int g = i & 31;
        *(uint4*)(smraw + row * BROW + g * 16) = gp[i];
    }
}

__global__ __launch_bounds__(256, 2) void mlp_fused_kernel(
    const unsigned short* __restrict__ Apack,
    int mat1, const float* __restrict__ bias1,
    int mat2, const float* __restrict__ bias2,
    float* __restrict__ Cf, int M)
{
    extern __shared__ char smraw[];

    const int tid = threadIdx.x;
    const int wid = tid >> 5;
    const int lane = tid & 31;
    const int gid = lane >> 2;
    const int tig = lane & 3;
    const int row0 = blockIdx.x * 128;
    const int rbase = wid * 16;

    char* Ubase = smraw + U_OFF + (wid * 8) * 512 + lane * 16;

    stage_B(smraw, mat1, tid);

    const uint4* Ap0 = (const uint4*)Apack + (size_t)(row0 + rbase + gid) * 32 + tig;
    const uint4* Ap1 = Ap0 + 8 * 32;

    float acc[16][4];
    #pragma unroll
    for (int nt = 0; nt < 16; nt++)
        acc[nt][0] = acc[nt][1] = acc[nt][2] = acc[nt][3] = 0.0f;

    uint4 c0a = Ap0[0], c0b = Ap1[0];
    uint4 c1a = Ap0[4], c1b = Ap1[4];

    __syncthreads();   // B1 ready

    // ---- Phase 1: U = A @ W1 ----
    #pragma unroll
    for (int kc = 0; kc < 8; kc++) {
        uint4 fa = c0a, fb = c0b;
        c0a = c1a; c0b = c1b;
        if (kc < 6) {
            c1a = Ap0[(kc + 2) * 4];
            c1b = Ap1[(kc + 2) * 4];
        }
        uint32_t ahi[4] = {fa.x, fb.x, fa.y, fb.y};
        uint32_t alo[4] = {fa.z, fb.z, fa.w, fb.w};

        const int koff = (kc * 4 + tig) * 16;
        #pragma unroll
        for (int nt = 0; nt < 16; nt++) {
            const int nrow = nt * 8 + gid;
            uint4 b = *(const uint4*)(smraw + nrow * BROW + koff);
            mma_bf16(acc[nt], ahi, b.x, b.y);
            mma_bf16(acc[nt], ahi, b.z, b.w);
            mma_bf16(acc[nt], alo, b.x, b.y);
        }
    }

    // ---- Convert: bias1 + silu + bf16 split. hi -> smem U, lo -> regs ----
    uint32_t ulo[8][4];
    #pragma unroll
    for (int kc = 0; kc < 8; kc++) {
        const int colA = kc * 16 + tig * 2;
        float2 bva = __ldg((const float2*)(bias1 + colA));
        float2 bvb = __ldg((const float2*)(bias1 + colA + 8));
        float v0x = silu(acc[2*kc][0] + bva.x),   v0y = silu(acc[2*kc][1] + bva.y);
        float v1x = silu(acc[2*kc][2] + bva.x),   v1y = silu(acc[2*kc][3] + bva.y);
        float v2x = silu(acc[2*kc+1][0] + bvb.x), v2y = silu(acc[2*kc+1][1] + bvb.y);
        float v3x = silu(acc[2*kc+1][2] + bvb.x), v3y = silu(acc[2*kc+1][3] + bvb.y);

        __nv_bfloat162 h0 = __floats2bfloat162_rn(v0x, v0y);
        __nv_bfloat162 h1 = __floats2bfloat162_rn(v1x, v1y);
        __nv_bfloat162 h2 = __floats2bfloat162_rn(v2x, v2y);
        __nv_bfloat162 h3 = __floats2bfloat162_rn(v3x, v3y);
        __nv_bfloat162 l0 = __floats2bfloat162_rn(v0x - __low2float(h0), v0y - __high2float(h0));
        __nv_bfloat162 l1 = __floats2bfloat162_rn(v1x - __low2float(h1), v1y - __high2float(h1));
        __nv_bfloat162 l2 = __floats2bfloat162_rn(v2x - __low2float(h2), v2y - __high2float(h2));
        __nv_bfloat162 l3 = __floats2bfloat162_rn(v3x - __low2float(h3), v3y - __high2float(h3));

        uint4 uh;
        uh.x = *(uint32_t*)&h0; uh.y = *(uint32_t*)&h1;
        uh.z = *(uint32_t*)&h2; uh.w = *(uint32_t*)&h3;
        *(uint4*)(Ubase + kc * 512) = uh;
        ulo[kc][0] = *(uint32_t*)&l0; ulo[kc][1] = *(uint32_t*)&l1;
        ulo[kc][2] = *(uint32_t*)&l2; ulo[kc][3] = *(uint32_t*)&l3;
    }

    __syncthreads();   // all B1 reads done; U hi written

    stage_B(smraw, mat2, tid);

    #pragma unroll
    for (int nt = 0; nt < 16; nt++)
        acc[nt][0] = acc[nt][1] = acc[nt][2] = acc[nt][3] = 0.0f;

    __syncthreads();   // B2 ready

    // ---- Phase 2: X' = U @ W2 ----
    #pragma unroll
    for (int kc = 0; kc < 8; kc++) {
        uint4 uh = *(const uint4*)(Ubase + kc * 512);
        uint32_t ahi[4] = {uh.x, uh.y, uh.z, uh.w};

        const int koff = (kc * 4 + tig) * 16;
        #pragma unroll
        for (int nt = 0; nt < 16; nt++) {
            const int nrow = nt * 8 + gid;
            uint4 b = *(const uint4*)(smraw + nrow * BROW + koff);
            mma_bf16(acc[nt], ahi, b.x, b.y);
            mma_bf16(acc[nt], ahi, b.z, b.w);
            mma_bf16(acc[nt], ulo[kc], b.x, b.y);
        }
    }

    // ---- Epilogue: bias2 + fp32 store ----
    const int rowA = row0 + rbase + gid;
    const int rowB = rowA + 8;
    #pragma unroll
    for (int kc = 0; kc < 8; kc++) {
        const int colA = kc * 16 + tig * 2;
        const int colB = colA + 8;
        float2 bva = __ldg((const float2*)(bias2 + colA));
        float2 bvb = __ldg((const float2*)(bias2 + colB));
        if (rowA < M) {
            *(float2*)(Cf + (size_t)rowA * H + colA) =
                make_float2(acc[2*kc][0] + bva.x, acc[2*kc][1] + bva.y);
            *(float2*)(Cf + (size_t)rowA * H + colB) =
                make_float2(acc[2*kc+1][0] + bvb.x, acc[2*kc+1][1] + bvb.y);
        }
        if (rowB < M) {
            *(float2*)(Cf + (size_t)rowB * H + colA) =
                make_float2(acc[2*kc][2] + bva.x, acc[2*kc][3] + bva.y);
            *(float2*)(Cf + (size_t)rowB * H + colB) =
                make_float2(acc[2*kc+1][2] + bvb.x, acc[2*kc+1][3] + bvb.y);
        }
    }
}

// ---------------------------------------------------------------------------
extern "C" void kernel_launch(void* const* d_in, const int* in_sizes, int n_in,
                              void* d_out, int out_size)
{
    const float* emb = (const float*)d_in[0];
    const float* We  = (const float*)d_in[1];
    const float* be  = (const float*)d_in[2];
    const float* W1  = (const float*)d_in[3];
    const float* b1  = (const float*)d_in[4];
    const float* W2  = (const float*)d_in[5];
    const float* b2  = (const float*)d_in[6];
    const float* ea  = (const float*)d_in[7];
    const int*   z   = (const int*)d_in[8];
    const int*   ei  = (const int*)d_in[9];
    const int*   bat = (const int*)d_in[10];

    const int N = in_sizes[8];
    const int E = in_sizes[9] / 2;
    float* out = (float*)d_out;

    float* x;
    unsigned short* aggp;
    cudaGetSymbolAddress((void**)&x, g_x);
    cudaGetSymbolAddress((void**)&aggp, g_aggp);

    cudaFuncSetAttribute(mlp_fused_kernel, cudaFuncAttributeMaxDynamicSharedMemorySize, MLP_SMEM);

    const bool has_tail = (size_t)out_size >= (size_t)N * H + (size_t)N;
    float* otail = has_tail ? (out + (size_t)N * H) : nullptr;

    // prep: weights pack + g_off zero + batch tail (one launch)
    {
        int tmax = (6 * 128 * 32 > N) ? 6 * 128 * 32 : N;
        prep_kernel<<<(tmax + 255) / 256, 256>>>(W1, W2, bat, otail, N);
    }

    // CSR build (once; graph static across layers)
    const int* srcp = ei;
    const int* dstp = ei + E;
    const int nb = (N + 1023) / 1024;
    csr_hist_kernel<<<(E + 255) / 256, 256>>>(dstp, E);
    csr_scan1_kernel<<<nb, 256>>>(N);
    csr_scan2_kernel<<<1, 128>>>(nb, N, E);
    csr_scan3_kernel<<<(N + 255) / 256, 256>>>(N);
    csr_scatter_kernel<<<(E + 255) / 256, 256>>>(dstp, E);

    const int tiles = (N + 127) / 128;
    const int agg_grid = (N * 32 + 255) / 256;

    for (int l = 0; l < 3; l++) {
        agg_pack_kernel<<<agg_grid, 256>>>(x, emb, z, srcp, ea,
                                           We + (size_t)l * 4 * H, be + (size_t)l * H,
                                           aggp, N, (l == 0) ? 1 : 0);
        mlp_fused_kernel<<<tiles, 256, MLP_SMEM>>>(
            aggp,
            l, b1 + (size_t)l * H,
            3 + l, b2 + (size_t)l * H,
            (l == 2) ? out : x, N);
    }
}

// round 14
// speedup vs baseline: 1.1204x; 1.1204x over previous
#include <cuda_runtime.h>
#include <cuda_bf16.h>
#include <cstdint>

#define H 128
#define MAXN 100000
#define MAXE 600000
#define MAXNP (MAXN + 128)   // pad so unguarded tail-tile accesses stay in bounds

// ---------------------------------------------------------------------------
// Scratch (__device__ globals; no allocation allowed)
// ---------------------------------------------------------------------------
__device__ float g_x[MAXNP * H];                       // fp32 node features
// Packed activations: per row, 32 uint4 groups; group (kc,tig) at index kc*4+tig
// = {hi(k,k+1), hi(k+8,k+9), lo(k,k+1), lo(k+8,k+9)}, k = kc*16 + tig*2.
__device__ unsigned short g_aggp[MAXNP * H * 2];       // packed agg (MLP input)
// Packed B fragments (weights), built once per call.
__device__ unsigned short g_Bpack[6 * 128 * 32 * 8];
// CSR
__device__ int g_rowptr[MAXN + 1];
__device__ int g_off[MAXN];
__device__ int g_bsum[128];
__device__ int g_eid[MAXE];

// ---------------------------------------------------------------------------
// Prep: packed B fragments + zero g_off (CSR hist init) + batch tail output.
// ---------------------------------------------------------------------------
__global__ void prep_kernel(const float* __restrict__ W1,
                            const float* __restrict__ W2,
                            const int* __restrict__ bat,
                            float* __restrict__ otail,
                            int N)
{
    int i = blockIdx.x * blockDim.x + threadIdx.x;

    if (i < 6 * 128 * 32) {
        int g = i;
        int mat = g >> 12;
        int r = g & 4095;
        int nrow = r >> 5;
        int q = r & 31;
        int kc = q >> 2;
        int tig = q & 3;
        int k = kc * 16 + tig * 2;

        const float* W = (mat < 3) ? (W1 + (size_t)mat * H * H)
                                   : (W2 + (size_t)(mat - 3) * H * H);
        unsigned short s[8];
        int kk[4] = {k, k + 1, k + 8, k + 9};
        #pragma unroll
        for (int j = 0; j < 4; j++) {
            float v = W[kk[j] * H + nrow];
            __nv_bfloat16 hi = __float2bfloat16(v);
            float res = v - __bfloat162float(hi);
            __nv_bfloat16 lo = __float2bfloat16(res);
            s[j] = __bfloat16_as_ushort(hi);
            s[4 + j] = __bfloat16_as_ushort(lo);
        }
        uint4 out;
        out.x = (uint32_t)s[0] | ((uint32_t)s[1] << 16);
        out.y = (uint32_t)s[2] | ((uint32_t)s[3] << 16);
        out.z = (uint32_t)s[4] | ((uint32_t)s[5] << 16);
        out.w = (uint32_t)s[6] | ((uint32_t)s[7] << 16);
        ((uint4*)g_Bpack)[g] = out;
    }
    if (i < N) {
        g_off[i] = 0;
        if (otail) otail[i] = (float)bat[i];
    }
}

// ---------------------------------------------------------------------------
// x[i] = emb[z[i]]
// ---------------------------------------------------------------------------
__global__ void embed_kernel(const float* __restrict__ emb,
                             const int* __restrict__ z,
                             float* __restrict__ x, int N)
{
    int i = blockIdx.x * blockDim.x + threadIdx.x;
    if (i >= N * (H / 4)) return;
    int row = i >> 5;
    int c = i & 31;
    ((float4*)x)[i] = ((const float4*)(emb + (size_t)z[row] * H))[c];
}

// ---------------------------------------------------------------------------
// CSR build (once per call; graph static across layers)
// ---------------------------------------------------------------------------
__global__ void csr_hist_kernel(const int* __restrict__ dst, int E)
{
    int e = blockIdx.x * blockDim.x + threadIdx.x;
    if (e < E) atomicAdd(&g_off[dst[e]], 1);
}
__global__ void csr_scan1_kernel(int N)
{
    __shared__ int ts[256];
    int b = blockIdx.x, t = threadIdx.x;
    int base = b * 1024 + t * 4;
    int v0 = (base + 0 < N) ? g_off[base + 0] : 0;
    int v1 = (base + 1 < N) ? g_off[base + 1] : 0;
    int v2 = (base + 2 < N) ? g_off[base + 2] : 0;
    int v3 = (base + 3 < N) ? g_off[base + 3] : 0;
    int s = v0 + v1 + v2 + v3;
    ts[t] = s;
    __syncthreads();
    for (int d = 1; d < 256; d <<= 1) {
        int xv = (t >= d) ? ts[t - d] : 0;
        __syncthreads();
        ts[t] += xv;
        __syncthreads();
    }
    int run = ts[t] - s;
    if (t == 255) g_bsum[b] = ts[255];
    if (base + 0 < N) g_rowptr[base + 0] = run;  run += v0;
    if (base + 1 < N) g_rowptr[base + 1] = run;  run += v1;
    if (base + 2 < N) g_rowptr[base + 2] = run;  run += v2;
    if (base + 3 < N) g_rowptr[base + 3] = run;
}
__global__ void csr_scan2_kernel(int nb, int N, int E)
{
    __shared__ int sv[128];
    int t = threadIdx.x;
    if (t < nb) sv[t] = g_bsum[t];
    __syncthreads();
    if (t == 0) {
        int run = 0;
        for (int i = 0; i < nb; i++) { int v = sv[i]; sv[i] = run; run += v; }
        g_rowptr[N] = E;
    }
    __syncthreads();
    if (t < nb) g_bsum[t] = sv[t];
}
__global__ void csr_scan3_kernel(int N)
{
    int i = blockIdx.x * blockDim.x + threadIdx.x;
    if (i < N) {
        int r = g_rowptr[i] + g_bsum[i >> 10];
        g_rowptr[i] = r;
        g_off[i] = r;
    }
}
__global__ void csr_scatter_kernel(const int* __restrict__ dst, int E)
{
    int e = blockIdx.x * blockDim.x + threadIdx.x;
    if (e < E) {
        int pos = atomicAdd(&g_off[dst[e]], 1);
        g_eid[pos] = e;
    }
}

// ---------------------------------------------------------------------------
// Aggregate (CSR, no atomics): one warp per node; output packed bf16 hi/lo.
// (R12 form — L2-bandwidth-bound; latency tricks regressed it in R13.)
// ---------------------------------------------------------------------------
__global__ __launch_bounds__(256) void agg_pack_kernel(
    const float* __restrict__ x,
    const int* __restrict__ src,
    const float* __restrict__ ea,
    const float* __restrict__ We,
    const float* __restrict__ be,
    unsigned short* __restrict__ Apack,
    int N)
{
    int warp = (blockIdx.x * blockDim.x + threadIdx.x) >> 5;
    if (warp >= N) return;
    const int n = warp;
    const int lane = threadIdx.x & 31;
    const int k0 = ((lane >> 2) << 4) + ((lane & 3) << 1);

    const float2 w0a = *(const float2*)(We + 0 * H + k0);
    const float2 w0b = *(const float2*)(We + 0 * H + k0 + 8);
    const float2 w1a = *(const float2*)(We + 1 * H + k0);
    const float2 w1b = *(const float2*)(We + 1 * H + k0 + 8);
    const float2 w2a = *(const float2*)(We + 2 * H + k0);
    const float2 w2b = *(const float2*)(We + 2 * H + k0 + 8);
    const float2 w3a = *(const float2*)(We + 3 * H + k0);
    const float2 w3b = *(const float2*)(We + 3 * H + k0 + 8);
    const float2 bea = *(const float2*)(be + k0);
    const float2 beb = *(const float2*)(be + k0 + 8);

    float2 sa = *(const float2*)(x + (size_t)n * H + k0);
    float2 sb = *(const float2*)(x + (size_t)n * H + k0 + 8);

    const int beg = g_rowptr[n], end = g_rowptr[n + 1];
    for (int i = beg; i < end; i++) {
        int e = __ldg(g_eid + i);
        int s = __ldg(src + e);
        float4 av = *(const float4*)(ea + 4 * (size_t)e);

        float2 pa, pb;
        pa.x = bea.x + av.x * w0a.x + av.y * w1a.x + av.z * w2a.x + av.w * w3a.x;
        pa.y = bea.y + av.x * w0a.y + av.y * w1a.y + av.z * w2a.y + av.w * w3a.y;
        pb.x = beb.x + av.x * w0b.x + av.y * w1b.x + av.z * w2b.x + av.w * w3b.x;
        pb.y = beb.y + av.x * w0b.y + av.y * w1b.y + av.z * w2b.y + av.w * w3b.y;

        float2 xa = *(const float2*)(x + (size_t)s * H + k0);
        float2 xb = *(const float2*)(x + (size_t)s * H + k0 + 8);
        sa.x += fmaxf(xa.x + pa.x, 0.0f);
        sa.y += fmaxf(xa.y + pa.y, 0.0f);
        sb.x += fmaxf(xb.x + pb.x, 0.0f);
        sb.y += fmaxf(xb.y + pb.y, 0.0f);
    }

    __nv_bfloat162 ha = __floats2bfloat162_rn(sa.x, sa.y);
    __nv_bfloat162 hb = __floats2bfloat162_rn(sb.x, sb.y);
    __nv_bfloat162 la = __floats2bfloat162_rn(sa.x - __low2float(ha), sa.y - __high2float(ha));
    __nv_bfloat162 lb = __floats2bfloat162_rn(sb.x - __low2float(hb), sb.y - __high2float(hb));
    uint4 pk;
    pk.x = *(uint32_t*)&ha; pk.y = *(uint32_t*)&hb;
    pk.z = *(uint32_t*)&la; pk.w = *(uint32_t*)&lb;
    ((uint4*)Apack)[(size_t)n * 32 + lane] = pk;
}

// ---------------------------------------------------------------------------
// Fused MLP (both GEMMs, one kernel), split-bf16 fp32 emulation:
//   X' = (silu(A @ W1 + b1)) @ W2 + b2
// Fragment identity: thread (gid,tig)'s phase-1 C-fragments for tiles
// nt=2kc,2kc+1 ARE its phase-2 A-fragment for k-chunk kc. U is fully
// register-resident (uhi+ulo, 64 regs); phase 2 runs nt-outer in 4 groups
// of 4 so live accumulators shrink to 16 regs. Smem holds only B (73.7KB).
// ---------------------------------------------------------------------------
#define BROW 576
#define MLP_SMEM (128 * BROW)                      // 73728 B -> 2 CTAs/SM

__device__ __forceinline__ void mma_bf16(float* c, const uint32_t* a,
                                         uint32_t b0, uint32_t b1)
{
    asm volatile(
        "mma.sync.aligned.m16n8k16.row.col.f32.bf16.bf16.f32 "
        "{%0,%1,%2,%3}, {%4,%5,%6,%7}, {%8,%9}, {%0,%1,%2,%3};"
        : "+f"(c[0]), "+f"(c[1]), "+f"(c[2]), "+f"(c[3])
        : "r"(a[0]), "r"(a[1]), "r"(a[2]), "r"(a[3]), "r"(b0), "r"(b1));
}

__device__ __forceinline__ float silu(float v) { return v / (1.0f + __expf(-v)); }

__device__ __forceinline__ void stage_B(char* smraw, int mat, int tid)
{
    const uint4* gp = (const uint4*)g_Bpack + (size_t)mat * 4096;
    #pragma unroll
    for (int it = 0; it < 16; it++) {
        int i = tid + it * 256;
        int row = i >> 5;
        int g = i & 31;
        *(uint4*)(smraw + row * BROW + g * 16) = gp[i];
    }
}

__global__ __launch_bounds__(256, 2) void mlp_fused_kernel(
    const unsigned short* __restrict__ Apack,
    int mat1, const float* __restrict__ bias1,
    int mat2, const float* __restrict__ bias2,
    float* __restrict__ Cf, int M)
{
    extern __shared__ char smraw[];

    const int tid = threadIdx.x;
    const int wid = tid >> 5;
    const int lane = tid & 31;
    const int gid = lane >> 2;
    const int tig = lane & 3;
    const int row0 = blockIdx.x * 128;
    const int rbase = wid * 16;

    stage_B(smraw, mat1, tid);

    const uint4* Ap0 = (const uint4*)Apack + (size_t)(row0 + rbase + gid) * 32 + tig;
    const uint4* Ap1 = Ap0 + 8 * 32;

    float acc[16][4];
    #pragma unroll
    for (int nt = 0; nt < 16; nt++)
        acc[nt][0] = acc[nt][1] = acc[nt][2] = acc[nt][3] = 0.0f;

    uint4 c0a = Ap0[0], c0b = Ap1[0];
    uint4 c1a = Ap0[4], c1b = Ap1[4];

    __syncthreads();   // B1 ready

    // ---- Phase 1: U = A @ W1 ----
    #pragma unroll
    for (int kc = 0; kc < 8; kc++) {
        uint4 fa = c0a, fb = c0b;
        c0a = c1a; c0b = c1b;
        if (kc < 6) {
            c1a = Ap0[(kc + 2) * 4];
            c1b = Ap1[(kc + 2) * 4];
        }
        uint32_t ahi[4] = {fa.x, fb.x, fa.y, fb.y};
        uint32_t alo[4] = {fa.z, fb.z, fa.w, fb.w};

        const int koff = (kc * 4 + tig) * 16;
        #pragma unroll
        for (int nt = 0; nt < 16; nt++) {
            const int nrow = nt * 8 + gid;
            uint4 b = *(const uint4*)(smraw + nrow * BROW + koff);
            mma_bf16(acc[nt], ahi, b.x, b.y);
            mma_bf16(acc[nt], ahi, b.z, b.w);
            mma_bf16(acc[nt], alo, b.x, b.y);
        }
    }

    // ---- Convert: bias1 + silu + bf16 split, all register-resident ----
    uint32_t uhi[8][4], ulo[8][4];
    #pragma unroll
    for (int kc = 0; kc < 8; kc++) {
        const int colA = kc * 16 + tig * 2;
        float2 bva = __ldg((const float2*)(bias1 + colA));
        float2 bvb = __ldg((const float2*)(bias1 + colA + 8));
        // a0 = (row gid, k,k+1), a1 = (row gid+8, k,k+1),
        // a2 = (row gid, k+8,+9), a3 = (row gid+8, k+8,+9)
        float v0x = silu(acc[2*kc][0] + bva.x),   v0y = silu(acc[2*kc][1] + bva.y);
        float v1x = silu(acc[2*kc][2] + bva.x),   v1y = silu(acc[2*kc][3] + bva.y);
        float v2x = silu(acc[2*kc+1][0] + bvb.x), v2y = silu(acc[2*kc+1][1] + bvb.y);
        float v3x = silu(acc[2*kc+1][2] + bvb.x), v3y = silu(acc[2*kc+1][3] + bvb.y);

        __nv_bfloat162 h0 = __floats2bfloat162_rn(v0x, v0y);
        __nv_bfloat162 h1 = __floats2bfloat162_rn(v1x, v1y);
        __nv_bfloat162 h2 = __floats2bfloat162_rn(v2x, v2y);
        __nv_bfloat162 h3 = __floats2bfloat162_rn(v3x, v3y);
        __nv_bfloat162 l0 = __floats2bfloat162_rn(v0x - __low2float(h0), v0y - __high2float(h0));
        __nv_bfloat162 l1 = __floats2bfloat162_rn(v1x - __low2float(h1), v1y - __high2float(h1));
        __nv_bfloat162 l2 = __floats2bfloat162_rn(v2x - __low2float(h2), v2y - __high2float(h2));
        __nv_bfloat162 l3 = __floats2bfloat162_rn(v3x - __low2float(h3), v3y - __high2float(h3));

        uhi[kc][0] = *(uint32_t*)&h0; uhi[kc][1] = *(uint32_t*)&h1;
        uhi[kc][2] = *(uint32_t*)&h2; uhi[kc][3] = *(uint32_t*)&h3;
        ulo[kc][0] = *(uint32_t*)&l0; ulo[kc][1] = *(uint32_t*)&l1;
        ulo[kc][2] = *(uint32_t*)&l2; ulo[kc][3] = *(uint32_t*)&l3;
    }

    __syncthreads();   // all B1 reads done

    stage_B(smraw, mat2, tid);

    __syncthreads();   // B2 ready

    // ---- Phase 2: X' = U @ W2, nt-outer (4 groups of 4), direct store ----
    const int rowA = row0 + rbase + gid;
    const int rowB = rowA + 8;
    #pragma unroll
    for (int ng = 0; ng < 4; ng++) {
        float a2[4][4];
        #pragma unroll
        for (int j = 0; j < 4; j++)
            a2[j][0] = a2[j][1] = a2[j][2] = a2[j][3] = 0.0f;

        #pragma unroll
        for (int kc = 0; kc < 8; kc++) {
            const int koff = (kc * 4 + tig) * 16;
            #pragma unroll
            for (int j = 0; j < 4; j++) {
                const int nrow = (ng * 4 + j) * 8 + gid;
                uint4 b = *(const uint4*)(smraw + nrow * BROW + koff);
                mma_bf16(a2[j], uhi[kc], b.x, b.y);
                mma_bf16(a2[j], uhi[kc], b.z, b.w);
                mma_bf16(a2[j], ulo[kc], b.x, b.y);
            }
        }

        #pragma unroll
        for (int j = 0; j < 4; j++) {
            const int col = (ng * 4 + j) * 8 + tig * 2;
            float2 bv = __ldg((const float2*)(bias2 + col));
            if (rowA < M)
                *(float2*)(Cf + (size_t)rowA * H + col) =
                    make_float2(a2[j][0] + bv.x, a2[j][1] + bv.y);
            if (rowB < M)
                *(float2*)(Cf + (size_t)rowB * H + col) =
                    make_float2(a2[j][2] + bv.x, a2[j][3] + bv.y);
        }
    }
}

// ---------------------------------------------------------------------------
extern "C" void kernel_launch(void* const* d_in, const int* in_sizes, int n_in,
                              void* d_out, int out_size)
{
    const float* emb = (const float*)d_in[0];
    const float* We  = (const float*)d_in[1];
    const float* be  = (const float*)d_in[2];
    const float* W1  = (const float*)d_in[3];
    const float* b1  = (const float*)d_in[4];
    const float* W2  = (const float*)d_in[5];
    const float* b2  = (const float*)d_in[6];
    const float* ea  = (const float*)d_in[7];
    const int*   z   = (const int*)d_in[8];
    const int*   ei  = (const int*)d_in[9];
    const int*   bat = (const int*)d_in[10];

    const int N = in_sizes[8];
    const int E = in_sizes[9] / 2;
    float* out = (float*)d_out;

    float* x;
    unsigned short* aggp;
    cudaGetSymbolAddress((void**)&x, g_x);
    cudaGetSymbolAddress((void**)&aggp, g_aggp);

    cudaFuncSetAttribute(mlp_fused_kernel, cudaFuncAttributeMaxDynamicSharedMemorySize, MLP_SMEM);

    const bool has_tail = (size_t)out_size >= (size_t)N * H + (size_t)N;
    float* otail = has_tail ? (out + (size_t)N * H) : nullptr;

    // prep: weights pack + g_off zero + batch tail (one launch)
    {
        int tmax = (6 * 128 * 32 > N) ? 6 * 128 * 32 : N;
        prep_kernel<<<(tmax + 255) / 256, 256>>>(W1, W2, bat, otail, N);
    }

    // CSR build (once; graph static across layers)
    const int* srcp = ei;
    const int* dstp = ei + E;
    const int nb = (N + 1023) / 1024;
    csr_hist_kernel<<<(E + 255) / 256, 256>>>(dstp, E);
    csr_scan1_kernel<<<nb, 256>>>(N);
    csr_scan2_kernel<<<1, 128>>>(nb, N, E);
    csr_scan3_kernel<<<(N + 255) / 256, 256>>>(N);
    csr_scatter_kernel<<<(E + 255) / 256, 256>>>(dstp, E);

    embed_kernel<<<(N * (H / 4) + 255) / 256, 256>>>(emb, z, x, N);

    const int tiles = (N + 127) / 128;
    const int agg_grid = (N * 32 + 255) / 256;

    for (int l = 0; l < 3; l++) {
        agg_pack_kernel<<<agg_grid, 256>>>(x, srcp, ea,
                                           We + (size_t)l * 4 * H, be + (size_t)l * H,
                                           aggp, N);
        mlp_fused_kernel<<<tiles, 256, MLP_SMEM>>>(
            aggp,
            l, b1 + (size_t)l * H,
            3 + l, b2 + (size_t)l * H,
            (l == 2) ? out : x, N);
    }
}

// round 15
// speedup vs baseline: 1.1810x; 1.0541x over previous
#include <cuda_runtime.h>
#include <cuda_bf16.h>
#include <cstdint>

#define H 128
#define MAXN 100000
#define MAXE 600000
#define MAXNP (MAXN + 128)   // pad so unguarded tail-tile accesses stay in bounds

// ---------------------------------------------------------------------------
// Scratch (__device__ globals; no allocation allowed)
// ---------------------------------------------------------------------------
__device__ float g_x[MAXNP * H];                       // fp32 node features
// Packed activations: per row, 32 uint4 groups; group (kc,tig) at index kc*4+tig
// = {hi(k,k+1), hi(k+8,k+9), lo(k,k+1), lo(k+8,k+9)}, k = kc*16 + tig*2.
__device__ unsigned short g_aggp[MAXNP * H * 2];       // packed agg (MLP input)
// Packed B fragments (weights), built once per call.
__device__ unsigned short g_Bpack[6 * 128 * 32 * 8];
// CSR
__device__ int g_rowptr[MAXN + 1];
__device__ int g_off[MAXN];
__device__ int g_bsum[128];
__device__ int g_eid[MAXE];

// ---------------------------------------------------------------------------
// Prep: packed B fragments + zero g_off (CSR hist init) + batch tail output.
// ---------------------------------------------------------------------------
__global__ void prep_kernel(const float* __restrict__ W1,
                            const float* __restrict__ W2,
                            const int* __restrict__ bat,
                            float* __restrict__ otail,
                            int N)
{
    int i = blockIdx.x * blockDim.x + threadIdx.x;

    if (i < 6 * 128 * 32) {
        int g = i;
        int mat = g >> 12;
        int r = g & 4095;
        int nrow = r >> 5;
        int q = r & 31;
        int kc = q >> 2;
        int tig = q & 3;
        int k = kc * 16 + tig * 2;

        const float* W = (mat < 3) ? (W1 + (size_t)mat * H * H)
                                   : (W2 + (size_t)(mat - 3) * H * H);
        unsigned short s[8];
        int kk[4] = {k, k + 1, k + 8, k + 9};
        #pragma unroll
        for (int j = 0; j < 4; j++) {
            float v = W[kk[j] * H + nrow];
            __nv_bfloat16 hi = __float2bfloat16(v);
            float res = v - __bfloat162float(hi);
            __nv_bfloat16 lo = __float2bfloat16(res);
            s[j] = __bfloat16_as_ushort(hi);
            s[4 + j] = __bfloat16_as_ushort(lo);
        }
        uint4 out;
        out.x = (uint32_t)s[0] | ((uint32_t)s[1] << 16);
        out.y = (uint32_t)s[2] | ((uint32_t)s[3] << 16);
        out.z = (uint32_t)s[4] | ((uint32_t)s[5] << 16);
        out.w = (uint32_t)s[6] | ((uint32_t)s[7] << 16);
        ((uint4*)g_Bpack)[g] = out;
    }
    if (i < N) {
        g_off[i] = 0;
        if (otail) otail[i] = (float)bat[i];
    }
}

// ---------------------------------------------------------------------------
// x[i] = emb[z[i]]
// ---------------------------------------------------------------------------
__global__ void embed_kernel(const float* __restrict__ emb,
                             const int* __restrict__ z,
                             float* __restrict__ x, int N)
{
    int i = blockIdx.x * blockDim.x + threadIdx.x;
    if (i >= N * (H / 4)) return;
    int row = i >> 5;
    int c = i & 31;
    ((float4*)x)[i] = ((const float4*)(emb + (size_t)z[row] * H))[c];
}

// ---------------------------------------------------------------------------
// CSR build (once per call; graph static across layers)
// ---------------------------------------------------------------------------
__global__ void csr_hist_kernel(const int* __restrict__ dst, int E)
{
    int e = blockIdx.x * blockDim.x + threadIdx.x;
    if (e < E) atomicAdd(&g_off[dst[e]], 1);
}
__global__ void csr_scan1_kernel(int N)
{
    __shared__ int ts[256];
    int b = blockIdx.x, t = threadIdx.x;
    int base = b * 1024 + t * 4;
    int v0 = (base + 0 < N) ? g_off[base + 0] : 0;
    int v1 = (base + 1 < N) ? g_off[base + 1] : 0;
    int v2 = (base + 2 < N) ? g_off[base + 2] : 0;
    int v3 = (base + 3 < N) ? g_off[base + 3] : 0;
    int s = v0 + v1 + v2 + v3;
    ts[t] = s;
    __syncthreads();
    for (int d = 1; d < 256; d <<= 1) {
        int xv = (t >= d) ? ts[t - d] : 0;
        __syncthreads();
        ts[t] += xv;
        __syncthreads();
    }
    int run = ts[t] - s;
    if (t == 255) g_bsum[b] = ts[255];
    if (base + 0 < N) g_rowptr[base + 0] = run;  run += v0;
    if (base + 1 < N) g_rowptr[base + 1] = run;  run += v1;
    if (base + 2 < N) g_rowptr[base + 2] = run;  run += v2;
    if (base + 3 < N) g_rowptr[base + 3] = run;
}
__global__ void csr_scan2_kernel(int nb, int N, int E)
{
    __shared__ int sv[128];
    int t = threadIdx.x;
    if (t < nb) sv[t] = g_bsum[t];
    __syncthreads();
    if (t == 0) {
        int run = 0;
        for (int i = 0; i < nb; i++) { int v = sv[i]; sv[i] = run; run += v; }
        g_rowptr[N] = E;
    }
    __syncthreads();
    if (t < nb) g_bsum[t] = sv[t];
}
__global__ void csr_scan3_kernel(int N)
{
    int i = blockIdx.x * blockDim.x + threadIdx.x;
    if (i < N) {
        int r = g_rowptr[i] + g_bsum[i >> 10];
        g_rowptr[i] = r;
        g_off[i] = r;
    }
}
__global__ void csr_scatter_kernel(const int* __restrict__ dst, int E)
{
    int e = blockIdx.x * blockDim.x + threadIdx.x;
    if (e < E) {
        int pos = atomicAdd(&g_off[dst[e]], 1);
        g_eid[pos] = e;
    }
}

// ---------------------------------------------------------------------------
// Aggregate (CSR, no atomics): one warp per node; output packed bf16 hi/lo.
// (R12/R14 form — L2-bandwidth-bound; latency tricks regressed it in R13.)
// ---------------------------------------------------------------------------
__global__ __launch_bounds__(256) void agg_pack_kernel(
    const float* __restrict__ x,
    const int* __restrict__ src,
    const float* __restrict__ ea,
    const float* __restrict__ We,
    const float* __restrict__ be,
    unsigned short* __restrict__ Apack,
    int N)
{
    int warp = (blockIdx.x * blockDim.x + threadIdx.x) >> 5;
    if (warp >= N) return;
    const int n = warp;
    const int lane = threadIdx.x & 31;
    const int k0 = ((lane >> 2) << 4) + ((lane & 3) << 1);

    const float2 w0a = *(const float2*)(We + 0 * H + k0);
    const float2 w0b = *(const float2*)(We + 0 * H + k0 + 8);
    const float2 w1a = *(const float2*)(We + 1 * H + k0);
    const float2 w1b = *(const float2*)(We + 1 * H + k0 + 8);
    const float2 w2a = *(const float2*)(We + 2 * H + k0);
    const float2 w2b = *(const float2*)(We + 2 * H + k0 + 8);
    const float2 w3a = *(const float2*)(We + 3 * H + k0);
    const float2 w3b = *(const float2*)(We + 3 * H + k0 + 8);
    const float2 bea = *(const float2*)(be + k0);
    const float2 beb = *(const float2*)(be + k0 + 8);

    float2 sa = *(const float2*)(x + (size_t)n * H + k0);
    float2 sb = *(const float2*)(x + (size_t)n * H + k0 + 8);

    const int beg = g_rowptr[n], end = g_rowptr[n + 1];
    for (int i = beg; i < end; i++) {
        int e = __ldg(g_eid + i);
        int s = __ldg(src + e);
        float4 av = *(const float4*)(ea + 4 * (size_t)e);

        float2 pa, pb;
        pa.x = bea.x + av.x * w0a.x + av.y * w1a.x + av.z * w2a.x + av.w * w3a.x;
        pa.y = bea.y + av.x * w0a.y + av.y * w1a.y + av.z * w2a.y + av.w * w3a.y;
        pb.x = beb.x + av.x * w0b.x + av.y * w1b.x + av.z * w2b.x + av.w * w3b.x;
        pb.y = beb.y + av.x * w0b.y + av.y * w1b.y + av.z * w2b.y + av.w * w3b.y;

        float2 xa = *(const float2*)(x + (size_t)s * H + k0);
        float2 xb = *(const float2*)(x + (size_t)s * H + k0 + 8);
        sa.x += fmaxf(xa.x + pa.x, 0.0f);
        sa.y += fmaxf(xa.y + pa.y, 0.0f);
        sb.x += fmaxf(xb.x + pb.x, 0.0f);
        sb.y += fmaxf(xb.y + pb.y, 0.0f);
    }

    __nv_bfloat162 ha = __floats2bfloat162_rn(sa.x, sa.y);
    __nv_bfloat162 hb = __floats2bfloat162_rn(sb.x, sb.y);
    __nv_bfloat162 la = __floats2bfloat162_rn(sa.x - __low2float(ha), sa.y - __high2float(ha));
    __nv_bfloat162 lb = __floats2bfloat162_rn(sb.x - __low2float(hb), sb.y - __high2float(hb));
    uint4 pk;
    pk.x = *(uint32_t*)&ha; pk.y = *(uint32_t*)&hb;
    pk.z = *(uint32_t*)&la; pk.w = *(uint32_t*)&lb;
    ((uint4*)Apack)[(size_t)n * 32 + lane] = pk;
}

// ---------------------------------------------------------------------------
// Persistent fused MLP: X' = (silu(A @ W1 + b1)) @ W2 + b2
// 148 CTAs x 512 threads, 1 CTA/SM. BOTH weight images resident in smem
// (147 KB), staged ONCE per CTA. Warps then stream 16-row chunks fully
// independently — no __syncthreads() in the loop. U (uhi+ulo) register-
// resident via the phase-1-C == phase-2-A fragment identity.
// ---------------------------------------------------------------------------
#define BROW 576
#define B2_OFF (128 * BROW)                        // 73728
#define MLP_SMEM (2 * 128 * BROW)                  // 147456 B -> 1 CTA/SM

__device__ __forceinline__ void mma_bf16(float* c, const uint32_t* a,
                                         uint32_t b0, uint32_t b1)
{
    asm volatile(
        "mma.sync.aligned.m16n8k16.row.col.f32.bf16.bf16.f32 "
        "{%0,%1,%2,%3}, {%4,%5,%6,%7}, {%8,%9}, {%0,%1,%2,%3};"
        : "+f"(c[0]), "+f"(c[1]), "+f"(c[2]), "+f"(c[3])
        : "r"(a[0]), "r"(a[1]), "r"(a[2]), "r"(a[3]), "r"(b0), "r"(b1));
}

__device__ __forceinline__ float silu(float v) { return v / (1.0f + __expf(-v)); }

__global__ __launch_bounds__(512, 1) void mlp_fused_kernel(
    const unsigned short* __restrict__ Apack,
    int mat1, const float* __restrict__ bias1,
    int mat2, const float* __restrict__ bias2,
    float* __restrict__ Cf, int M)
{
    extern __shared__ char smraw[];

    const int tid = threadIdx.x;
    const int wid = tid >> 5;
    const int lane = tid & 31;
    const int gid = lane >> 2;
    const int tig = lane & 3;

    // ---- Stage BOTH weight images once (8192 uint4 over 512 threads) ----
    {
        const uint4* gp1 = (const uint4*)g_Bpack + (size_t)mat1 * 4096;
        const uint4* gp2 = (const uint4*)g_Bpack + (size_t)mat2 * 4096;
        #pragma unroll
        for (int it = 0; it < 8; it++) {
            int i = tid + it * 512;
            int row = i >> 5;
            int g = i & 31;
            *(uint4*)(smraw + row * BROW + g * 16) = gp1[i];
            *(uint4*)(smraw + B2_OFF + row * BROW + g * 16) = gp2[i];
        }
    }
    __syncthreads();   // only sync in the kernel

    const int nchunks = (M + 15) >> 4;
    const int total_warps = gridDim.x * 16;

    for (int chunk = blockIdx.x * 16 + wid; chunk < nchunks; chunk += total_warps) {
        const int rowA = chunk * 16 + gid;
        const int rowB = rowA + 8;

        const uint4* Ap0 = (const uint4*)Apack + (size_t)rowA * 32 + tig;
        const uint4* Ap1 = Ap0 + 8 * 32;

        float acc[16][4];
        #pragma unroll
        for (int nt = 0; nt < 16; nt++)
            acc[nt][0] = acc[nt][1] = acc[nt][2] = acc[nt][3] = 0.0f;

        uint4 c0a = Ap0[0], c0b = Ap1[0];
        uint4 c1a = Ap0[4], c1b = Ap1[4];

        // ---- Phase 1: U = A @ W1 ----
        #pragma unroll
        for (int kc = 0; kc < 8; kc++) {
            uint4 fa = c0a, fb = c0b;
            c0a = c1a; c0b = c1b;
            if (kc < 6) {
                c1a = Ap0[(kc + 2) * 4];
                c1b = Ap1[(kc + 2) * 4];
            }
            uint32_t ahi[4] = {fa.x, fb.x, fa.y, fb.y};
            uint32_t alo[4] = {fa.z, fb.z, fa.w, fb.w};

            const int koff = (kc * 4 + tig) * 16;
            #pragma unroll
            for (int nt = 0; nt < 16; nt++) {
                const int nrow = nt * 8 + gid;
                uint4 b = *(const uint4*)(smraw + nrow * BROW + koff);
                mma_bf16(acc[nt], ahi, b.x, b.y);
                mma_bf16(acc[nt], ahi, b.z, b.w);
                mma_bf16(acc[nt], alo, b.x, b.y);
            }
        }

        // ---- Convert: bias1 + silu + bf16 split, register-resident ----
        uint32_t uhi[8][4], ulo[8][4];
        #pragma unroll
        for (int kc = 0; kc < 8; kc++) {
            const int colA = kc * 16 + tig * 2;
            float2 bva = __ldg((const float2*)(bias1 + colA));
            float2 bvb = __ldg((const float2*)(bias1 + colA + 8));
            float v0x = silu(acc[2*kc][0] + bva.x),   v0y = silu(acc[2*kc][1] + bva.y);
            float v1x = silu(acc[2*kc][2] + bva.x),   v1y = silu(acc[2*kc][3] + bva.y);
            float v2x = silu(acc[2*kc+1][0] + bvb.x), v2y = silu(acc[2*kc+1][1] + bvb.y);
            float v3x = silu(acc[2*kc+1][2] + bvb.x), v3y = silu(acc[2*kc+1][3] + bvb.y);

            __nv_bfloat162 h0 = __floats2bfloat162_rn(v0x, v0y);
            __nv_bfloat162 h1 = __floats2bfloat162_rn(v1x, v1y);
            __nv_bfloat162 h2 = __floats2bfloat162_rn(v2x, v2y);
            __nv_bfloat162 h3 = __floats2bfloat162_rn(v3x, v3y);
            __nv_bfloat162 l0 = __floats2bfloat162_rn(v0x - __low2float(h0), v0y - __high2float(h0));
            __nv_bfloat162 l1 = __floats2bfloat162_rn(v1x - __low2float(h1), v1y - __high2float(h1));
            __nv_bfloat162 l2 = __floats2bfloat162_rn(v2x - __low2float(h2), v2y - __high2float(h2));
            __nv_bfloat162 l3 = __floats2bfloat162_rn(v3x - __low2float(h3), v3y - __high2float(h3));

            uhi[kc][0] = *(uint32_t*)&h0; uhi[kc][1] = *(uint32_t*)&h1;
            uhi[kc][2] = *(uint32_t*)&h2; uhi[kc][3] = *(uint32_t*)&h3;
            ulo[kc][0] = *(uint32_t*)&l0; ulo[kc][1] = *(uint32_t*)&l1;
            ulo[kc][2] = *(uint32_t*)&l2; ulo[kc][3] = *(uint32_t*)&l3;
        }

        // ---- Phase 2: X' = U @ W2, nt-outer (4 groups of 4), direct store ----
        #pragma unroll
        for (int ng = 0; ng < 4; ng++) {
            float a2[4][4];
            #pragma unroll
            for (int j = 0; j < 4; j++)
                a2[j][0] = a2[j][1] = a2[j][2] = a2[j][3] = 0.0f;

            #pragma unroll
            for (int kc = 0; kc < 8; kc++) {
                const int koff = (kc * 4 + tig) * 16;
                #pragma unroll
                for (int j = 0; j < 4; j++) {
                    const int nrow = (ng * 4 + j) * 8 + gid;
                    uint4 b = *(const uint4*)(smraw + B2_OFF + nrow * BROW + koff);
                    mma_bf16(a2[j], uhi[kc], b.x, b.y);
                    mma_bf16(a2[j], uhi[kc], b.z, b.w);
                    mma_bf16(a2[j], ulo[kc], b.x, b.y);
                }
            }

            #pragma unroll
            for (int j = 0; j < 4; j++) {
                const int col = (ng * 4 + j) * 8 + tig * 2;
                float2 bv = __ldg((const float2*)(bias2 + col));
                if (rowA < M)
                    *(float2*)(Cf + (size_t)rowA * H + col) =
                        make_float2(a2[j][0] + bv.x, a2[j][1] + bv.y);
                if (rowB < M)
                    *(float2*)(Cf + (size_t)rowB * H + col) =
                        make_float2(a2[j][2] + bv.x, a2[j][3] + bv.y);
            }
        }
    }
}

// ---------------------------------------------------------------------------
extern "C" void kernel_launch(void* const* d_in, const int* in_sizes, int n_in,
                              void* d_out, int out_size)
{
    const float* emb = (const float*)d_in[0];
    const float* We  = (const float*)d_in[1];
    const float* be  = (const float*)d_in[2];
    const float* W1  = (const float*)d_in[3];
    const float* b1  = (const float*)d_in[4];
    const float* W2  = (const float*)d_in[5];
    const float* b2  = (const float*)d_in[6];
    const float* ea  = (const float*)d_in[7];
    const int*   z   = (const int*)d_in[8];
    const int*   ei  = (const int*)d_in[9];
    const int*   bat = (const int*)d_in[10];

    const int N = in_sizes[8];
    const int E = in_sizes[9] / 2;
    float* out = (float*)d_out;

    float* x;
    unsigned short* aggp;
    cudaGetSymbolAddress((void**)&x, g_x);
    cudaGetSymbolAddress((void**)&aggp, g_aggp);

    cudaFuncSetAttribute(mlp_fused_kernel, cudaFuncAttributeMaxDynamicSharedMemorySize, MLP_SMEM);

    const bool has_tail = (size_t)out_size >= (size_t)N * H + (size_t)N;
    float* otail = has_tail ? (out + (size_t)N * H) : nullptr;

    // prep: weights pack + g_off zero + batch tail (one launch)
    {
        int tmax = (6 * 128 * 32 > N) ? 6 * 128 * 32 : N;
        prep_kernel<<<(tmax + 255) / 256, 256>>>(W1, W2, bat, otail, N);
    }

    // CSR build (once; graph static across layers)
    const int* srcp = ei;
    const int* dstp = ei + E;
    const int nb = (N + 1023) / 1024;
    csr_hist_kernel<<<(E + 255) / 256, 256>>>(dstp, E);
    csr_scan1_kernel<<<nb, 256>>>(N);
    csr_scan2_kernel<<<1, 128>>>(nb, N, E);
    csr_scan3_kernel<<<(N + 255) / 256, 256>>>(N);
    csr_scatter_kernel<<<(E + 255) / 256, 256>>>(dstp, E);

    embed_kernel<<<(N * (H / 4) + 255) / 256, 256>>>(emb, z, x, N);

    const int agg_grid = (N * 32 + 255) / 256;

    for (int l = 0; l < 3; l++) {
        agg_pack_kernel<<<agg_grid, 256>>>(x, srcp, ea,
                                           We + (size_t)l * 4 * H, be + (size_t)l * H,
                                           aggp, N);
        mlp_fused_kernel<<<148, 512, MLP_SMEM>>>(
            aggp,
            l, b1 + (size_t)l * H,
            3 + l, b2 + (size_t)l * H,
            (l == 2) ? out : x, N);
    }
}

// round 16
// speedup vs baseline: 1.2911x; 1.0932x over previous
#include <cuda_runtime.h>
#include <cuda_bf16.h>
#include <cstdint>

#define H 128
#define MAXN 100000
#define MAXE 600000
#define MAXNP (MAXN + 128)   // pad so unguarded tail-tile accesses stay in bounds

// ---------------------------------------------------------------------------
// Scratch (__device__ globals; no allocation allowed)
// ---------------------------------------------------------------------------
__device__ float g_x[MAXNP * H];                       // fp32 node features
// Packed activations: per row, 32 uint4 groups; group (kc,tig) at index kc*4+tig
// = {hi(k,k+1), hi(k+8,k+9), lo(k,k+1), lo(k+8,k+9)}, k = kc*16 + tig*2.
__device__ unsigned short g_aggp[MAXNP * H * 2];       // packed agg (MLP input)
// Packed B fragments (weights), built once per call.
__device__ unsigned short g_Bpack[6 * 128 * 32 * 8];
// CSR (edge data reordered into CSR order: no eid indirection in agg)
__device__ int g_rowptr[MAXN + 1];
__device__ int g_off[MAXN];
__device__ int g_bsum[128];
__device__ int g_csrc[MAXE];                           // src node, CSR order
__device__ float4 g_cea[MAXE];                         // edge_attr, CSR order

// ---------------------------------------------------------------------------
// Prep: packed B fragments + zero g_off (CSR hist init) + batch tail output.
// ---------------------------------------------------------------------------
__global__ void prep_kernel(const float* __restrict__ W1,
                            const float* __restrict__ W2,
                            const int* __restrict__ bat,
                            float* __restrict__ otail,
                            int N)
{
    int i = blockIdx.x * blockDim.x + threadIdx.x;

    if (i < 6 * 128 * 32) {
        int g = i;
        int mat = g >> 12;
        int r = g & 4095;
        int nrow = r >> 5;
        int q = r & 31;
        int kc = q >> 2;
        int tig = q & 3;
        int k = kc * 16 + tig * 2;

        const float* W = (mat < 3) ? (W1 + (size_t)mat * H * H)
                                   : (W2 + (size_t)(mat - 3) * H * H);
        unsigned short s[8];
        int kk[4] = {k, k + 1, k + 8, k + 9};
        #pragma unroll
        for (int j = 0; j < 4; j++) {
            float v = W[kk[j] * H + nrow];
            __nv_bfloat16 hi = __float2bfloat16(v);
            float res = v - __bfloat162float(hi);
            __nv_bfloat16 lo = __float2bfloat16(res);
            s[j] = __bfloat16_as_ushort(hi);
            s[4 + j] = __bfloat16_as_ushort(lo);
        }
        uint4 out;
        out.x = (uint32_t)s[0] | ((uint32_t)s[1] << 16);
        out.y = (uint32_t)s[2] | ((uint32_t)s[3] << 16);
        out.z = (uint32_t)s[4] | ((uint32_t)s[5] << 16);
        out.w = (uint32_t)s[6] | ((uint32_t)s[7] << 16);
        ((uint4*)g_Bpack)[g] = out;
    }
    if (i < N) {
        g_off[i] = 0;
        if (otail) otail[i] = (float)bat[i];
    }
}

// ---------------------------------------------------------------------------
// x[i] = emb[z[i]]
// ---------------------------------------------------------------------------
__global__ void embed_kernel(const float* __restrict__ emb,
                             const int* __restrict__ z,
                             float* __restrict__ x, int N)
{
    int i = blockIdx.x * blockDim.x + threadIdx.x;
    if (i >= N * (H / 4)) return;
    int row = i >> 5;
    int c = i & 31;
    ((float4*)x)[i] = ((const float4*)(emb + (size_t)z[row] * H))[c];
}

// ---------------------------------------------------------------------------
// CSR build (once per call; graph static across layers)
// ---------------------------------------------------------------------------
__global__ void csr_hist_kernel(const int* __restrict__ dst, int E)
{
    int e = blockIdx.x * blockDim.x + threadIdx.x;
    if (e < E) atomicAdd(&g_off[dst[e]], 1);
}
__global__ void csr_scan1_kernel(int N)
{
    __shared__ int ts[256];
    int b = blockIdx.x, t = threadIdx.x;
    int base = b * 1024 + t * 4;
    int v0 = (base + 0 < N) ? g_off[base + 0] : 0;
    int v1 = (base + 1 < N) ? g_off[base + 1] : 0;
    int v2 = (base + 2 < N) ? g_off[base + 2] : 0;
    int v3 = (base + 3 < N) ? g_off[base + 3] : 0;
    int s = v0 + v1 + v2 + v3;
    ts[t] = s;
    __syncthreads();
    for (int d = 1; d < 256; d <<= 1) {
        int xv = (t >= d) ? ts[t - d] : 0;
        __syncthreads();
        ts[t] += xv;
        __syncthreads();
    }
    int run = ts[t] - s;
    if (t == 255) g_bsum[b] = ts[255];
    if (base + 0 < N) g_rowptr[base + 0] = run;  run += v0;
    if (base + 1 < N) g_rowptr[base + 1] = run;  run += v1;
    if (base + 2 < N) g_rowptr[base + 2] = run;  run += v2;
    if (base + 3 < N) g_rowptr[base + 3] = run;
}
// scan3 with scan2 fused: warp 0 recomputes the <=98-entry block-sum prefix
// in smem (raw aggregates from scan1), then all threads apply it.
__global__ void csr_scan3_kernel(int N, int nb, int E)
{
    __shared__ int pre[129];
    int t = threadIdx.x;
    if (t == 0) {
        int run = 0;
        for (int j = 0; j < nb; j++) { pre[j] = run; run += g_bsum[j]; }
    }
    __syncthreads();
    int i = blockIdx.x * blockDim.x + t;
    if (i == 0) g_rowptr[N] = E;
    if (i < N) {
        int r = g_rowptr[i] + pre[i >> 10];
        g_rowptr[i] = r;
        g_off[i] = r;
    }
}
// Scatter edge data directly into CSR order (src + edge_attr), no eid.
__global__ void csr_scatter_kernel(const int* __restrict__ src,
                                   const int* __restrict__ dst,
                                   const float* __restrict__ ea, int E)
{
    int e = blockIdx.x * blockDim.x + threadIdx.x;
    if (e < E) {
        int pos = atomicAdd(&g_off[dst[e]], 1);
        g_csrc[pos] = src[e];
        g_cea[pos] = *(const float4*)(ea + 4 * (size_t)e);
    }
}

// ---------------------------------------------------------------------------
// Aggregate (CSR, no atomics): one warp per node; output packed bf16 hi/lo.
// Edge data read from CSR-ordered csrc/cea: 2-deep load chain, contiguous ea.
// ---------------------------------------------------------------------------
__global__ __launch_bounds__(256) void agg_pack_kernel(
    const float* __restrict__ x,
    const float* __restrict__ We,
    const float* __restrict__ be,
    unsigned short* __restrict__ Apack,
    int N)
{
    int warp = (blockIdx.x * blockDim.x + threadIdx.x) >> 5;
    if (warp >= N) return;
    const int n = warp;
    const int lane = threadIdx.x & 31;
    const int k0 = ((lane >> 2) << 4) + ((lane & 3) << 1);

    const float2 w0a = *(const float2*)(We + 0 * H + k0);
    const float2 w0b = *(const float2*)(We + 0 * H + k0 + 8);
    const float2 w1a = *(const float2*)(We + 1 * H + k0);
    const float2 w1b = *(const float2*)(We + 1 * H + k0 + 8);
    const float2 w2a = *(const float2*)(We + 2 * H + k0);
    const float2 w2b = *(const float2*)(We + 2 * H + k0 + 8);
    const float2 w3a = *(const float2*)(We + 3 * H + k0);
    const float2 w3b = *(const float2*)(We + 3 * H + k0 + 8);
    const float2 bea = *(const float2*)(be + k0);
    const float2 beb = *(const float2*)(be + k0 + 8);

    float2 sa = *(const float2*)(x + (size_t)n * H + k0);
    float2 sb = *(const float2*)(x + (size_t)n * H + k0 + 8);

    const int beg = g_rowptr[n], end = g_rowptr[n + 1];
    for (int i = beg; i < end; i++) {
        int s = __ldg(g_csrc + i);
        float4 av = g_cea[i];

        float2 pa, pb;
        pa.x = bea.x + av.x * w0a.x + av.y * w1a.x + av.z * w2a.x + av.w * w3a.x;
        pa.y = bea.y + av.x * w0a.y + av.y * w1a.y + av.z * w2a.y + av.w * w3a.y;
        pb.x = beb.x + av.x * w0b.x + av.y * w1b.x + av.z * w2b.x + av.w * w3b.x;
        pb.y = beb.y + av.x * w0b.y + av.y * w1b.y + av.z * w2b.y + av.w * w3b.y;

        float2 xa = *(const float2*)(x + (size_t)s * H + k0);
        float2 xb = *(const float2*)(x + (size_t)s * H + k0 + 8);
        sa.x += fmaxf(xa.x + pa.x, 0.0f);
        sa.y += fmaxf(xa.y + pa.y, 0.0f);
        sb.x += fmaxf(xb.x + pb.x, 0.0f);
        sb.y += fmaxf(xb.y + pb.y, 0.0f);
    }

    __nv_bfloat162 ha = __floats2bfloat162_rn(sa.x, sa.y);
    __nv_bfloat162 hb = __floats2bfloat162_rn(sb.x, sb.y);
    __nv_bfloat162 la = __floats2bfloat162_rn(sa.x - __low2float(ha), sa.y - __high2float(ha));
    __nv_bfloat162 lb = __floats2bfloat162_rn(sb.x - __low2float(hb), sb.y - __high2float(hb));
    uint4 pk;
    pk.x = *(uint32_t*)&ha; pk.y = *(uint32_t*)&hb;
    pk.z = *(uint32_t*)&la; pk.w = *(uint32_t*)&lb;
    ((uint4*)Apack)[(size_t)n * 32 + lane] = pk;
}

// ---------------------------------------------------------------------------
// Persistent fused MLP: X' = (silu(A @ W1 + b1)) @ W2 + b2
// 148 CTAs x 512 threads, 1 CTA/SM. BOTH weight images resident in smem
// (147 KB), staged ONCE per CTA. Warps stream 16-row chunks independently —
// no __syncthreads() in the loop. U (uhi+ulo) register-resident.
// ---------------------------------------------------------------------------
#define BROW 576
#define B2_OFF (128 * BROW)                        // 73728
#define MLP_SMEM (2 * 128 * BROW)                  // 147456 B -> 1 CTA/SM

__device__ __forceinline__ void mma_bf16(float* c, const uint32_t* a,
                                         uint32_t b0, uint32_t b1)
{
    asm volatile(
        "mma.sync.aligned.m16n8k16.row.col.f32.bf16.bf16.f32 "
        "{%0,%1,%2,%3}, {%4,%5,%6,%7}, {%8,%9}, {%0,%1,%2,%3};"
        : "+f"(c[0]), "+f"(c[1]), "+f"(c[2]), "+f"(c[3])
        : "r"(a[0]), "r"(a[1]), "r"(a[2]), "r"(a[3]), "r"(b0), "r"(b1));
}

__device__ __forceinline__ float silu(float v) { return v / (1.0f + __expf(-v)); }

__global__ __launch_bounds__(512, 1) void mlp_fused_kernel(
    const unsigned short* __restrict__ Apack,
    int mat1, const float* __restrict__ bias1,
    int mat2, const float* __restrict__ bias2,
    float* __restrict__ Cf, int M)
{
    extern __shared__ char smraw[];

    const int tid = threadIdx.x;
    const int wid = tid >> 5;
    const int lane = tid & 31;
    const int gid = lane >> 2;
    const int tig = lane & 3;

    // ---- Stage BOTH weight images once (8192 uint4 over 512 threads) ----
    {
        const uint4* gp1 = (const uint4*)g_Bpack + (size_t)mat1 * 4096;
        const uint4* gp2 = (const uint4*)g_Bpack + (size_t)mat2 * 4096;
        #pragma unroll
        for (int it = 0; it < 8; it++) {
            int i = tid + it * 512;
            int row = i >> 5;
            int g = i & 31;
            *(uint4*)(smraw + row * BROW + g * 16) = gp1[i];
            *(uint4*)(smraw + B2_OFF + row * BROW + g * 16) = gp2[i];
        }
    }
    __syncthreads();   // only sync in the kernel

    const int nchunks = (M + 15) >> 4;
    const int total_warps = gridDim.x * 16;

    for (int chunk = blockIdx.x * 16 + wid; chunk < nchunks; chunk += total_warps) {
        const int rowA = chunk * 16 + gid;
        const int rowB = rowA + 8;

        const uint4* Ap0 = (const uint4*)Apack + (size_t)rowA * 32 + tig;
        const uint4* Ap1 = Ap0 + 8 * 32;

        float acc[16][4];
        #pragma unroll
        for (int nt = 0; nt < 16; nt++)
            acc[nt][0] = acc[nt][1] = acc[nt][2] = acc[nt][3] = 0.0f;

        uint4 c0a = Ap0[0], c0b = Ap1[0];
        uint4 c1a = Ap0[4], c1b = Ap1[4];

        // ---- Phase 1: U = A @ W1 ----
        #pragma unroll
        for (int kc = 0; kc < 8; kc++) {
            uint4 fa = c0a, fb = c0b;
            c0a = c1a; c0b = c1b;
            if (kc < 6) {
                c1a = Ap0[(kc + 2) * 4];
                c1b = Ap1[(kc + 2) * 4];
            }
            uint32_t ahi[4] = {fa.x, fb.x, fa.y, fb.y};
            uint32_t alo[4] = {fa.z, fb.z, fa.w, fb.w};

            const int koff = (kc * 4 + tig) * 16;
            #pragma unroll
            for (int nt = 0; nt < 16; nt++) {
                const int nrow = nt * 8 + gid;
                uint4 b = *(const uint4*)(smraw + nrow * BROW + koff);
                mma_bf16(acc[nt], ahi, b.x, b.y);
                mma_bf16(acc[nt], ahi, b.z, b.w);
                mma_bf16(acc[nt], alo, b.x, b.y);
            }
        }

        // ---- Convert: bias1 + silu + bf16 split, register-resident ----
        uint32_t uhi[8][4], ulo[8][4];
        #pragma unroll
        for (int kc = 0; kc < 8; kc++) {
            const int colA = kc * 16 + tig * 2;
            float2 bva = __ldg((const float2*)(bias1 + colA));
            float2 bvb = __ldg((const float2*)(bias1 + colA + 8));
            float v0x = silu(acc[2*kc][0] + bva.x),   v0y = silu(acc[2*kc][1] + bva.y);
            float v1x = silu(acc[2*kc][2] + bva.x),   v1y = silu(acc[2*kc][3] + bva.y);
            float v2x = silu(acc[2*kc+1][0] + bvb.x), v2y = silu(acc[2*kc+1][1] + bvb.y);
            float v3x = silu(acc[2*kc+1][2] + bvb.x), v3y = silu(acc[2*kc+1][3] + bvb.y);

            __nv_bfloat162 h0 = __floats2bfloat162_rn(v0x, v0y);
            __nv_bfloat162 h1 = __floats2bfloat162_rn(v1x, v1y);
            __nv_bfloat162 h2 = __floats2bfloat162_rn(v2x, v2y);
            __nv_bfloat162 h3 = __floats2bfloat162_rn(v3x, v3y);
            __nv_bfloat162 l0 = __floats2bfloat162_rn(v0x - __low2float(h0), v0y - __high2float(h0));
            __nv_bfloat162 l1 = __floats2bfloat162_rn(v1x - __low2float(h1), v1y - __high2float(h1));
            __nv_bfloat162 l2 = __floats2bfloat162_rn(v2x - __low2float(h2), v2y - __high2float(h2));
            __nv_bfloat162 l3 = __floats2bfloat162_rn(v3x - __low2float(h3), v3y - __high2float(h3));

            uhi[kc][0] = *(uint32_t*)&h0; uhi[kc][1] = *(uint32_t*)&h1;
            uhi[kc][2] = *(uint32_t*)&h2; uhi[kc][3] = *(uint32_t*)&h3;
            ulo[kc][0] = *(uint32_t*)&l0; ulo[kc][1] = *(uint32_t*)&l1;
            ulo[kc][2] = *(uint32_t*)&l2; ulo[kc][3] = *(uint32_t*)&l3;
        }

        // ---- Phase 2: X' = U @ W2, nt-outer (4 groups of 4), direct store ----
        #pragma unroll
        for (int ng = 0; ng < 4; ng++) {
            float a2[4][4];
            #pragma unroll
            for (int j = 0; j < 4; j++)
                a2[j][0] = a2[j][1] = a2[j][2] = a2[j][3] = 0.0f;

            #pragma unroll
            for (int kc = 0; kc < 8; kc++) {
                const int koff = (kc * 4 + tig) * 16;
                #pragma unroll
                for (int j = 0; j < 4; j++) {
                    const int nrow = (ng * 4 + j) * 8 + gid;
                    uint4 b = *(const uint4*)(smraw + B2_OFF + nrow * BROW + koff);
                    mma_bf16(a2[j], uhi[kc], b.x, b.y);
                    mma_bf16(a2[j], uhi[kc], b.z, b.w);
                    mma_bf16(a2[j], ulo[kc], b.x, b.y);
                }
            }

            #pragma unroll
            for (int j = 0; j < 4; j++) {
                const int col = (ng * 4 + j) * 8 + tig * 2;
                float2 bv = __ldg((const float2*)(bias2 + col));
                if (rowA < M)
                    *(float2*)(Cf + (size_t)rowA * H + col) =
                        make_float2(a2[j][0] + bv.x, a2[j][1] + bv.y);
                if (rowB < M)
                    *(float2*)(Cf + (size_t)rowB * H + col) =
                        make_float2(a2[j][2] + bv.x, a2[j][3] + bv.y);
            }
        }
    }
}

// ---------------------------------------------------------------------------
extern "C" void kernel_launch(void* const* d_in, const int* in_sizes, int n_in,
                              void* d_out, int out_size)
{
    const float* emb = (const float*)d_in[0];
    const float* We  = (const float*)d_in[1];
    const float* be  = (const float*)d_in[2];
    const float* W1  = (const float*)d_in[3];
    const float* b1  = (const float*)d_in[4];
    const float* W2  = (const float*)d_in[5];
    const float* b2  = (const float*)d_in[6];
    const float* ea  = (const float*)d_in[7];
    const int*   z   = (const int*)d_in[8];
    const int*   ei  = (const int*)d_in[9];
    const int*   bat = (const int*)d_in[10];

    const int N = in_sizes[8];
    const int E = in_sizes[9] / 2;
    float* out = (float*)d_out;

    float* x;
    unsigned short* aggp;
    cudaGetSymbolAddress((void**)&x, g_x);
    cudaGetSymbolAddress((void**)&aggp, g_aggp);

    cudaFuncSetAttribute(mlp_fused_kernel, cudaFuncAttributeMaxDynamicSharedMemorySize, MLP_SMEM);

    const bool has_tail = (size_t)out_size >= (size_t)N * H + (size_t)N;
    float* otail = has_tail ? (out + (size_t)N * H) : nullptr;

    // prep: weights pack + g_off zero + batch tail (one launch)
    {
        int tmax = (6 * 128 * 32 > N) ? 6 * 128 * 32 : N;
        prep_kernel<<<(tmax + 255) / 256, 256>>>(W1, W2, bat, otail, N);
    }

    // CSR build (once; graph static across layers)
    const int* srcp = ei;
    const int* dstp = ei + E;
    const int nb = (N + 1023) / 1024;
    csr_hist_kernel<<<(E + 255) / 256, 256>>>(dstp, E);
    csr_scan1_kernel<<<nb, 256>>>(N);
    csr_scan3_kernel<<<(N + 255) / 256, 256>>>(N, nb, E);
    csr_scatter_kernel<<<(E + 255) / 256, 256>>>(srcp, dstp, ea, E);

    embed_kernel<<<(N * (H / 4) + 255) / 256, 256>>>(emb, z, x, N);

    const int agg_grid = (N * 32 + 255) / 256;

    for (int l = 0; l < 3; l++) {
        agg_pack_kernel<<<agg_grid, 256>>>(x,
                                           We + (size_t)l * 4 * H, be + (size_t)l * H,
                                           aggp, N);
        mlp_fused_kernel<<<148, 512, MLP_SMEM>>>(
            aggp,
            l, b1 + (size_t)l * H,
            3 + l, b2 + (size_t)l * H,
            (l == 2) ? out : x, N);
    }
}